// round 4
// baseline (speedup 1.0000x reference)
#include <cuda_runtime.h>
#include <math.h>

// Problem constants (fixed by the reference).
#define BATCH 4096
#define DIM   768
#define KNEG  60
#define NLOG  (KNEG + 1)      // 61 logits per row
#define D4    (DIM / 4)       // 192 float4 per row
#define PER_LANE 6            // 192 / 32 lanes

// Per-row loss scratch (no device allocation allowed -> __device__ global).
__device__ float g_row_loss[BATCH];

// ---------------------------------------------------------------------------
// Kernel 1: one CTA per row. 8 warps; warp w computes logits j = w, w+8, ...
// Each lane holds a fixed 24-element slice of u[b] in registers (6x float4),
// reused for all 61 dot products. Item rows are gathered from L2.
// ---------------------------------------------------------------------------
__global__ __launch_bounds__(256, 8)
void u2i_row_kernel(const float* __restrict__ user,
                    const float* __restrict__ items,
                    const int*   __restrict__ negs)
{
    const int b    = blockIdx.x;
    const int tid  = threadIdx.x;
    const int warp = tid >> 5;
    const int lane = tid & 31;

    __shared__ int   s_idx[NLOG];
    __shared__ float s_logits[NLOG];

    // Logit 0 = positive (own row), logits 1..60 = gathered negatives.
    if (tid == 0)             s_idx[0]   = b;
    else if (tid <= KNEG)     s_idx[tid] = negs[b * KNEG + (tid - 1)];
    __syncthreads();

    // Load this lane's fixed slice of u[b] once (coalesced float4).
    const float4* u4 = reinterpret_cast<const float4*>(user + (size_t)b * DIM);
    float4 ur[PER_LANE];
#pragma unroll
    for (int i = 0; i < PER_LANE; i++)
        ur[i] = u4[lane + 32 * i];

    // 61 dot products, 8 per warp (last tranche handles j=56..60).
    for (int j = warp; j < NLOG; j += 8) {
        const float4* p4 =
            reinterpret_cast<const float4*>(items + (size_t)s_idx[j] * DIM);
        float acc = 0.0f;
#pragma unroll
        for (int i = 0; i < PER_LANE; i++) {
            float4 v = p4[lane + 32 * i];      // 6 independent LDG.128 -> MLP
            acc += v.x * ur[i].x + v.y * ur[i].y
                 + v.z * ur[i].z + v.w * ur[i].w;
        }
#pragma unroll
        for (int off = 16; off; off >>= 1)
            acc += __shfl_xor_sync(0xffffffffu, acc, off);
        if (lane == 0) s_logits[j] = acc;
    }
    __syncthreads();

    // Warp 0: 61-way logsumexp, loss = lse - logit[0].
    if (warp == 0) {
        const float NEG = -3.0e38f;           // expf underflows to exactly 0
        float a = (lane        < NLOG) ? s_logits[lane]      : NEG;
        float c = (lane + 32   < NLOG) ? s_logits[lane + 32] : NEG;

        float m = fmaxf(a, c);
#pragma unroll
        for (int off = 16; off; off >>= 1)
            m = fmaxf(m, __shfl_xor_sync(0xffffffffu, m, off));

        float s = expf(a - m) + expf(c - m);
#pragma unroll
        for (int off = 16; off; off >>= 1)
            s += __shfl_xor_sync(0xffffffffu, s, off);

        if (lane == 0)
            g_row_loss[b] = m + logf(s) - s_logits[0];
    }
}

// ---------------------------------------------------------------------------
// Kernel 2: deterministic single-block mean over the 4096 per-row losses.
// ---------------------------------------------------------------------------
__global__ void u2i_reduce_kernel(float* __restrict__ out)
{
    __shared__ float sm[256];
    const int tid = threadIdx.x;

    float s = 0.0f;
    for (int i = tid; i < BATCH; i += 256)
        s += g_row_loss[i];
    sm[tid] = s;
    __syncthreads();

#pragma unroll
    for (int st = 128; st; st >>= 1) {
        if (tid < st) sm[tid] += sm[tid + st];
        __syncthreads();
    }
    if (tid == 0)
        out[0] = sm[0] * (1.0f / (float)BATCH);
}

// ---------------------------------------------------------------------------
// Harness entry point. Inputs per metadata order:
//   d_in[0] = user_emb     f32 (4096*768)
//   d_in[1] = pos_item_emb f32 (4096*768)
//   d_in[2] = neg_indices  i32 (4096*60)
// d_out = f32 scalar.
// Graph-capturable: kernel launches only, no sync, no allocation.
// ---------------------------------------------------------------------------
extern "C" void kernel_launch(void* const* d_in, const int* in_sizes, int n_in,
                              void* d_out, int out_size)
{
    (void)in_sizes; (void)n_in; (void)out_size;
    const float* user  = (const float*)d_in[0];
    const float* items = (const float*)d_in[1];
    const int*   negs  = (const int*)  d_in[2];
    float*       out   = (float*)      d_out;

    u2i_row_kernel<<<BATCH, 256>>>(user, items, negs);
    u2i_reduce_kernel<<<1, 256>>>(out);
}

// round 6
// speedup vs baseline: 1.4714x; 1.4714x over previous
#include <cuda_runtime.h>
#include <cuda_bf16.h>
#include <math.h>

// Problem constants (fixed by the reference).
#define BATCH 4096
#define DIM   768
#define KNEG  60
#define NLOG  (KNEG + 1)      // 61 logits per row
#define CHUNKS 96             // DIM / 8 bf16-chunks of 16B
#define PER_LANE 3            // 96 / 32 lanes

// 16-byte chunk of 8 bf16 values.
struct alignas(16) BF8 { __nv_bfloat162 h[4]; };

// Scratch (no device allocation allowed -> __device__ globals).
__device__ BF8       g_items_bf16[BATCH * CHUNKS];   // 6.29 MB bf16 item table
__device__ float     g_row_loss[BATCH];
__device__ unsigned  g_done = 0;                     // last-block ticket

// ---------------------------------------------------------------------------
// Kernel 1: convert the fp32 item table to bf16 once per launch.
// Each thread converts 8 elements (2x float4 -> 1x BF8). Grid covers exactly
// BATCH*DIM/8 = 393216 threads.
// ---------------------------------------------------------------------------
__global__ __launch_bounds__(256)
void convert_items_kernel(const float* __restrict__ items)
{
    const unsigned t = blockIdx.x * 256u + threadIdx.x;   // chunk id
    const float4* in = reinterpret_cast<const float4*>(items);
    float4 a = in[2u * t];
    float4 b = in[2u * t + 1u];
    BF8 o;
    o.h[0] = __floats2bfloat162_rn(a.x, a.y);
    o.h[1] = __floats2bfloat162_rn(a.z, a.w);
    o.h[2] = __floats2bfloat162_rn(b.x, b.y);
    o.h[3] = __floats2bfloat162_rn(b.z, b.w);
    g_items_bf16[t] = o;
}

// ---------------------------------------------------------------------------
// Kernel 2: one CTA per row. 8 warps; warp w computes logits j = w, w+8, ...
// Each lane owns a fixed 24-element slice of u[b] (fp32, in registers),
// reused across all 61 dot products. Item rows are gathered as bf16 from L2
// (half the bytes of the fp32 version). Final mean is done by the last block
// to finish (threadfence-reduction) -> no separate reduce launch.
// ---------------------------------------------------------------------------
__global__ __launch_bounds__(256, 4)
void u2i_row_kernel(const float* __restrict__ user,
                    const int*   __restrict__ negs,
                    float*       __restrict__ out)
{
    const int b    = blockIdx.x;
    const int tid  = threadIdx.x;
    const int warp = tid >> 5;
    const int lane = tid & 31;

    __shared__ int   s_idx[NLOG];
    __shared__ float s_logits[NLOG];
    __shared__ bool  s_last;
    __shared__ float s_red[256];

    // Logit 0 = positive (own row), logits 1..60 = gathered negatives.
    if (tid == 0)          s_idx[0]   = b;
    else if (tid <= KNEG)  s_idx[tid] = negs[b * KNEG + (tid - 1)];
    __syncthreads();

    // Lane's fixed 24-element fp32 slice of u[b]: elements [8c, 8c+8) for
    // c = lane, lane+32, lane+64 -> float4 indices 2c and 2c+1.
    const float4* u4 = reinterpret_cast<const float4*>(user + (size_t)b * DIM);
    float4 uf[2 * PER_LANE];
#pragma unroll
    for (int i = 0; i < PER_LANE; i++) {
        const int c = lane + 32 * i;
        uf[2 * i]     = u4[2 * c];
        uf[2 * i + 1] = u4[2 * c + 1];
    }

    // 61 dot products, 8 per warp.
    for (int j = warp; j < NLOG; j += 8) {
        const BF8* p = g_items_bf16 + (size_t)s_idx[j] * CHUNKS;
        float acc = 0.0f;
#pragma unroll
        for (int i = 0; i < PER_LANE; i++) {
            BF8 raw = p[lane + 32 * i];          // 3 independent LDG.128
            const float2 v0 = __bfloat1622float2(raw.h[0]);
            const float2 v1 = __bfloat1622float2(raw.h[1]);
            const float2 v2 = __bfloat1622float2(raw.h[2]);
            const float2 v3 = __bfloat1622float2(raw.h[3]);
            const float4 uA = uf[2 * i];
            const float4 uB = uf[2 * i + 1];
            acc += v0.x * uA.x + v0.y * uA.y
                 + v1.x * uA.z + v1.y * uA.w
                 + v2.x * uB.x + v2.y * uB.y
                 + v3.x * uB.z + v3.y * uB.w;
        }
#pragma unroll
        for (int off = 16; off; off >>= 1)
            acc += __shfl_xor_sync(0xffffffffu, acc, off);
        if (lane == 0) s_logits[j] = acc;
    }
    __syncthreads();

    // Warp 0: 61-way logsumexp, loss = lse - logit[0]; then take a ticket.
    if (warp == 0) {
        const float NEG = -3.0e38f;              // expf underflows to 0
        float a = (lane      < NLOG) ? s_logits[lane]      : NEG;
        float c = (lane + 32 < NLOG) ? s_logits[lane + 32] : NEG;

        float m = fmaxf(a, c);
#pragma unroll
        for (int off = 16; off; off >>= 1)
            m = fmaxf(m, __shfl_xor_sync(0xffffffffu, m, off));

        float s = expf(a - m) + expf(c - m);
#pragma unroll
        for (int off = 16; off; off >>= 1)
            s += __shfl_xor_sync(0xffffffffu, s, off);

        if (lane == 0) {
            g_row_loss[b] = m + logf(s) - s_logits[0];
            __threadfence();
            s_last = (atomicAdd(&g_done, 1u) == BATCH - 1u);
        }
    }
    __syncthreads();

    // Last block to finish: deterministic fixed-order mean over all rows.
    if (s_last) {
        __threadfence();
        float s = 0.0f;
        for (int i = tid; i < BATCH; i += 256)
            s += __ldcg(&g_row_loss[i]);         // L2 load (skip L1)
        s_red[tid] = s;
        __syncthreads();
#pragma unroll
        for (int st = 128; st; st >>= 1) {
            if (tid < st) s_red[tid] += s_red[tid + st];
            __syncthreads();
        }
        if (tid == 0) {
            out[0] = s_red[0] * (1.0f / (float)BATCH);
            g_done = 0;                          // reset for next graph replay
        }
    }
}

// ---------------------------------------------------------------------------
// Harness entry point. Inputs per metadata order:
//   d_in[0] = user_emb     f32 (4096*768)
//   d_in[1] = pos_item_emb f32 (4096*768)
//   d_in[2] = neg_indices  i32 (4096*60)
// d_out = f32 scalar.
// Graph-capturable: two kernel launches, no sync, no allocation.
// ---------------------------------------------------------------------------
extern "C" void kernel_launch(void* const* d_in, const int* in_sizes, int n_in,
                              void* d_out, int out_size)
{
    (void)in_sizes; (void)n_in; (void)out_size;
    const float* user  = (const float*)d_in[0];
    const float* items = (const float*)d_in[1];
    const int*   negs  = (const int*)  d_in[2];
    float*       out   = (float*)      d_out;

    // BATCH*DIM/8 chunks / 256 threads = 1536 blocks (exact).
    convert_items_kernel<<<(BATCH * CHUNKS) / 256, 256>>>(items);
    u2i_row_kernel<<<BATCH, 256>>>(user, negs, out);
}

// round 11
// speedup vs baseline: 1.6456x; 1.1184x over previous
#include <cuda_runtime.h>
#include <cuda_bf16.h>
#include <math.h>

// Problem constants (fixed by the reference).
#define BATCH 4096
#define DIM   768
#define KNEG  60
#define NLOG  (KNEG + 1)      // 61 logits per row
#define CHUNKS 96             // DIM / 8 bf16-chunks of 16B
#define PER_LANE 3            // 96 / 32 lanes

typedef unsigned long long u64;

// 16-byte chunk of 8 bf16 values, viewed as 4x bf16x2 words.
struct alignas(16) BF8 { unsigned u[4]; };

// Scratch (no device allocation allowed -> __device__ globals).
__device__ BF8       g_items_bf16[BATCH * CHUNKS];   // 6.29 MB bf16 item table
__device__ float     g_row_loss[BATCH];
__device__ unsigned  g_done = 0;                     // last-block ticket

// ---- sm_103a packed-fp32 helpers (ptxas won't emit FFMA2 from plain C++) ----
__device__ __forceinline__ u64 pack_f32x2(float lo, float hi) {
    u64 r; asm("mov.b64 %0, {%1, %2};" : "=l"(r) : "f"(lo), "f"(hi)); return r;
}
// bf16x2 word (lo|hi) -> f32x2 pair: lo = w<<16, hi = w & 0xFFFF0000.
__device__ __forceinline__ u64 bf2_to_f32x2(unsigned w) {
    unsigned lo = w << 16, hi = w & 0xFFFF0000u;
    u64 r; asm("mov.b64 %0, {%1, %2};" : "=l"(r) : "r"(lo), "r"(hi)); return r;
}
__device__ __forceinline__ void ffma2(u64& d, u64 a, u64 b) {
    asm("fma.rn.f32x2 %0, %1, %2, %0;" : "+l"(d) : "l"(a), "l"(b));
}
__device__ __forceinline__ float hsum_f32x2(u64 a) {
    float lo, hi; asm("mov.b64 {%0, %1}, %2;" : "=f"(lo), "=f"(hi) : "l"(a));
    return lo + hi;
}
__device__ __forceinline__ unsigned pack_bf2(float x, float y) {
    __nv_bfloat162 t = __floats2bfloat162_rn(x, y);   // x -> low half
    return *reinterpret_cast<unsigned*>(&t);
}

// ---------------------------------------------------------------------------
// Kernel 1: convert the fp32 item table to bf16 (DRAM-bound, ~2.4us).
// ---------------------------------------------------------------------------
__global__ __launch_bounds__(256)
void convert_items_kernel(const float* __restrict__ items)
{
    const unsigned t = blockIdx.x * 256u + threadIdx.x;   // chunk id
    const float4* in = reinterpret_cast<const float4*>(items);
    float4 a = in[2u * t];
    float4 b = in[2u * t + 1u];
    BF8 o;
    o.u[0] = pack_bf2(a.x, a.y);
    o.u[1] = pack_bf2(a.z, a.w);
    o.u[2] = pack_bf2(b.x, b.y);
    o.u[3] = pack_bf2(b.z, b.w);
    g_items_bf16[t] = o;
}

// ---------------------------------------------------------------------------
// Kernel 2: one CTA per row. 8 warps; warp w computes logits {w, w+8, ...}.
// Two logits are processed per loop iteration (6 outstanding LDG.128/lane)
// and MACs use packed fp32x2 FFMA (2 MACs/instr). Each lane's fixed
// 24-element fp32 slice of u[b] lives in 12 register pairs, reused for all
// 61 dot products. Fused last-block mean (no separate reduce launch).
// ---------------------------------------------------------------------------
__global__ __launch_bounds__(256, 4)
void u2i_row_kernel(const float* __restrict__ user,
                    const int*   __restrict__ negs,
                    float*       __restrict__ out)
{
    const int b    = blockIdx.x;
    const int tid  = threadIdx.x;
    const int warp = tid >> 5;
    const int lane = tid & 31;

    __shared__ int   s_idx[NLOG];
    __shared__ float s_logits[NLOG];
    __shared__ bool  s_last;
    __shared__ float s_red[256];

    // Logit 0 = positive (own row), logits 1..60 = gathered negatives.
    if (tid == 0)          s_idx[0]   = b;
    else if (tid <= KNEG)  s_idx[tid] = negs[b * KNEG + (tid - 1)];
    __syncthreads();

    // Lane's fixed 24-element u-slice as 12 packed f32x2 registers.
    // Chunk c = lane + 32*i covers elements [8c, 8c+8).
    const float4* u4 = reinterpret_cast<const float4*>(user + (size_t)b * DIM);
    u64 uu[4 * PER_LANE];
#pragma unroll
    for (int i = 0; i < PER_LANE; i++) {
        const int c = lane + 32 * i;
        float4 a = u4[2 * c];
        float4 d = u4[2 * c + 1];
        uu[4 * i + 0] = pack_f32x2(a.x, a.y);
        uu[4 * i + 1] = pack_f32x2(a.z, a.w);
        uu[4 * i + 2] = pack_f32x2(d.x, d.y);
        uu[4 * i + 3] = pack_f32x2(d.z, d.w);
    }

    // 61 dot products, 2 per warp per iteration (j and j+8).
    for (int j = warp; j < NLOG; j += 16) {
        const int  j2   = j + 8;
        const bool has2 = (j2 < NLOG);
        const uint4* p1 = reinterpret_cast<const uint4*>(
            g_items_bf16 + (size_t)s_idx[j] * CHUNKS);
        const uint4* p2 = reinterpret_cast<const uint4*>(
            g_items_bf16 + (size_t)s_idx[has2 ? j2 : j] * CHUNKS);

        u64 acc1 = 0ull, acc2 = 0ull;
#pragma unroll
        for (int i = 0; i < PER_LANE; i++) {
            uint4 r1 = p1[lane + 32 * i];        // 6 independent LDG.128
            uint4 r2 = p2[lane + 32 * i];
            ffma2(acc1, bf2_to_f32x2(r1.x), uu[4 * i + 0]);
            ffma2(acc2, bf2_to_f32x2(r2.x), uu[4 * i + 0]);
            ffma2(acc1, bf2_to_f32x2(r1.y), uu[4 * i + 1]);
            ffma2(acc2, bf2_to_f32x2(r2.y), uu[4 * i + 1]);
            ffma2(acc1, bf2_to_f32x2(r1.z), uu[4 * i + 2]);
            ffma2(acc2, bf2_to_f32x2(r2.z), uu[4 * i + 2]);
            ffma2(acc1, bf2_to_f32x2(r1.w), uu[4 * i + 3]);
            ffma2(acc2, bf2_to_f32x2(r2.w), uu[4 * i + 3]);
        }
        float a1 = hsum_f32x2(acc1);
        float a2 = hsum_f32x2(acc2);
#pragma unroll
        for (int off = 16; off; off >>= 1) {      // interleaved reduce chains
            a1 += __shfl_xor_sync(0xffffffffu, a1, off);
            a2 += __shfl_xor_sync(0xffffffffu, a2, off);
        }
        if (lane == 0) {
            s_logits[j] = a1;
            if (has2) s_logits[j2] = a2;
        }
    }
    __syncthreads();

    // Warp 0: 61-way logsumexp, loss = lse - logit[0]; then take a ticket.
    if (warp == 0) {
        const float NEG = -3.0e38f;              // expf underflows to 0
        float a = (lane      < NLOG) ? s_logits[lane]      : NEG;
        float c = (lane + 32 < NLOG) ? s_logits[lane + 32] : NEG;

        float m = fmaxf(a, c);
#pragma unroll
        for (int off = 16; off; off >>= 1)
            m = fmaxf(m, __shfl_xor_sync(0xffffffffu, m, off));

        float s = expf(a - m) + expf(c - m);
#pragma unroll
        for (int off = 16; off; off >>= 1)
            s += __shfl_xor_sync(0xffffffffu, s, off);

        if (lane == 0) {
            g_row_loss[b] = m + logf(s) - s_logits[0];
            __threadfence();
            s_last = (atomicAdd(&g_done, 1u) == BATCH - 1u);
        }
    }
    __syncthreads();

    // Last block to finish: deterministic fixed-order mean over all rows.
    if (s_last) {
        __threadfence();
        float s = 0.0f;
        for (int i = tid; i < BATCH; i += 256)
            s += __ldcg(&g_row_loss[i]);
        s_red[tid] = s;
        __syncthreads();
#pragma unroll
        for (int st = 128; st; st >>= 1) {
            if (tid < st) s_red[tid] += s_red[tid + st];
            __syncthreads();
        }
        if (tid == 0) {
            out[0] = s_red[0] * (1.0f / (float)BATCH);
            g_done = 0;                          // reset for next graph replay
        }
    }
}

// ---------------------------------------------------------------------------
// Harness entry point. Inputs per metadata order:
//   d_in[0] = user_emb     f32 (4096*768)
//   d_in[1] = pos_item_emb f32 (4096*768)
//   d_in[2] = neg_indices  i32 (4096*60)
// d_out = f32 scalar.  Graph-capturable: two launches, no sync, no alloc.
// ---------------------------------------------------------------------------
extern "C" void kernel_launch(void* const* d_in, const int* in_sizes, int n_in,
                              void* d_out, int out_size)
{
    (void)in_sizes; (void)n_in; (void)out_size;
    const float* user  = (const float*)d_in[0];
    const float* items = (const float*)d_in[1];
    const int*   negs  = (const int*)  d_in[2];
    float*       out   = (float*)      d_out;

    convert_items_kernel<<<(BATCH * CHUNKS) / 256, 256>>>(items);
    u2i_row_kernel<<<BATCH, 256>>>(user, negs, out);
}